// round 2
// baseline (speedup 1.0000x reference)
#include <cuda_runtime.h>

#define NN 50000
#define EE 800000
#define FMAX 128

static __constant__ float kNEG = 0.2f;
#define EPS_BN 1e-5f

// ---------------- scratch (device globals; no allocation allowed) ----------
__device__ float g_h[NN * FMAX];     // transformed features  h = in @ W
__device__ float g_acc[NN * FMAX];   // unnormalized aggregation
__device__ float g_fa[NN * FMAX];    // node feature ping
__device__ float g_fb[NN * FMAX];    // node feature pong
__device__ float g_es[NN * 4];
__device__ float g_ed[NN * 4];
__device__ float g_den[NN * 4];
__device__ float g_bnsum[FMAX];
__device__ float g_bnsq[FMAX];
__device__ float g_scale[FMAX];
__device__ float g_shift[FMAX];

// ---------------- utility ---------------------------------------------------
__global__ void zero_k(float* p, int n) {
    int i = blockIdx.x * 256 + threadIdx.x;
    if (i < n) p[i] = 0.f;
}

// ---------------- GEMM: C[N,K] = A[N,M] @ W[M,K] ---------------------------
// block (32,8); each thread computes 4 consecutive rows of one column.
// A row loads are warp-uniform (broadcast), W loads are coalesced + L1-resident.
__global__ void gemm_k(const float* __restrict__ A, const float* __restrict__ W,
                       float* __restrict__ C, int M, int K) {
    int col = blockIdx.x * 32 + threadIdx.x;          // K is a multiple of 32
    int r0  = (blockIdx.y * 8 + threadIdx.y) * 4;
    // clamp row indices for safe loads, guard stores
    long o0 = (long)min(r0 + 0, NN - 1) * M;
    long o1 = (long)min(r0 + 1, NN - 1) * M;
    long o2 = (long)min(r0 + 2, NN - 1) * M;
    long o3 = (long)min(r0 + 3, NN - 1) * M;
    float a0 = 0.f, a1 = 0.f, a2 = 0.f, a3 = 0.f;
#pragma unroll 4
    for (int m = 0; m < M; m++) {
        float w = W[m * K + col];
        a0 = fmaf(w, A[o0 + m], a0);
        a1 = fmaf(w, A[o1 + m], a1);
        a2 = fmaf(w, A[o2 + m], a2);
        a3 = fmaf(w, A[o3 + m], a3);
    }
    if (r0 + 0 < NN) C[(long)(r0 + 0) * K + col] = a0;
    if (r0 + 1 < NN) C[(long)(r0 + 1) * K + col] = a1;
    if (r0 + 2 < NN) C[(long)(r0 + 2) * K + col] = a2;
    if (r0 + 3 < NN) C[(long)(r0 + 3) * K + col] = a3;
}

// ---------------- attention coefficients: es/ed[n,h] = h[n,h,:] . a[h,:] ---
__global__ void attn_k(const float* __restrict__ h, const float* __restrict__ asr,
                       const float* __restrict__ adt, float* __restrict__ es,
                       float* __restrict__ ed, int H, int D) {
    int i = blockIdx.x * blockDim.x + threadIdx.x;
    if (i >= NN * H) return;
    int n = i / H, hd = i - n * H;
    const float* hp = h + (long)n * H * D + hd * D;
    const float* a1 = asr + hd * D;
    const float* a2 = adt + hd * D;
    float s = 0.f, d = 0.f;
    for (int k = 0; k < D; k++) {
        float v = hp[k];
        s = fmaf(v, a1[k], s);
        d = fmaf(v, a2[k], d);
    }
    es[i] = s;
    ed[i] = d;
}

// ---------------- edge pass: one warp per edge ------------------------------
// ex = exp(lrelu(es[s]+ed[d]));  den[d] += ex;  acc[d,:] += ex * h[s,:]
template <int F, int H>
__global__ void edge_k(const int* __restrict__ src, const int* __restrict__ dst,
                       const float* __restrict__ h, const float* __restrict__ es,
                       const float* __restrict__ ed, float* den, float* acc) {
    int idx  = blockIdx.x * blockDim.x + threadIdx.x;
    int e    = idx >> 5;
    int lane = idx & 31;
    if (e >= EE) return;
    int s = src[e];
    int d = dst[e];
    constexpr int VEC = F / 32;
    constexpr int D   = F / H;
    int f0   = lane * VEC;
    int head = f0 / D;
    float a = es[s * H + head] + ed[d * H + head];
    a = a > 0.f ? a : kNEG * a;
    float ex = __expf(a);
    if ((f0 & (D - 1)) == 0)
        asm volatile("red.global.add.f32 [%0], %1;" ::"l"(&den[d * H + head]), "f"(ex));
    const float* hp = h + (long)s * F + f0;
    float* ap = acc + (long)d * F + f0;
    if (VEC == 4) {
        float4 hv = *(const float4*)hp;
        asm volatile("red.global.add.v4.f32 [%0], {%1,%2,%3,%4};" ::"l"(ap),
                     "f"(ex * hv.x), "f"(ex * hv.y), "f"(ex * hv.z), "f"(ex * hv.w));
    } else {
        asm volatile("red.global.add.f32 [%0], %1;" ::"l"(ap), "f"(ex * hp[0]));
    }
}

// ---------------- finalize: fold in self-loop, normalize, bias, relu -------
__global__ void fin_k(const float* __restrict__ h, const float* __restrict__ es,
                      const float* __restrict__ ed, const float* __restrict__ den,
                      const float* __restrict__ acc, const float* __restrict__ bias,
                      float* __restrict__ out, int F, int H, int relu) {
    int i = blockIdx.x * blockDim.x + threadIdx.x;
    if (i >= NN * F) return;
    int n = i / F, f = i - n * F;
    int D = F / H;
    int head = f / D;
    float a = es[n * H + head] + ed[n * H + head];
    a = a > 0.f ? a : kNEG * a;
    float ex = __expf(a);
    float v = (acc[i] + ex * h[i]) / (den[n * H + head] + ex) + bias[f];
    if (relu) v = fmaxf(v, 0.f);
    out[i] = v;
}

// ---------------- batchnorm -------------------------------------------------
__global__ void bn_part(const float* __restrict__ x, int F) {
    int c  = threadIdx.x;             // blockDim.x == F
    int r0 = blockIdx.x * 128;
    int r1 = min(r0 + 128, NN);
    float s = 0.f, s2 = 0.f;
    for (int r = r0; r < r1; r++) {
        float v = x[(long)r * F + c];
        s += v;
        s2 = fmaf(v, v, s2);
    }
    atomicAdd(&g_bnsum[c], s);
    atomicAdd(&g_bnsq[c], s2);
}

__global__ void bn_fin(const float* __restrict__ g, const float* __restrict__ be, int F) {
    int c = threadIdx.x;
    if (c >= F) return;
    float m   = g_bnsum[c] * (1.f / NN);
    float var = g_bnsq[c] * (1.f / NN) - m * m;
    float rs  = rsqrtf(var + EPS_BN);
    g_scale[c] = g[c] * rs;
    g_shift[c] = be[c] - m * g[c] * rs;
}

__global__ void bn_apply(float* __restrict__ x, int F, int relu) {
    int i = blockIdx.x * blockDim.x + threadIdx.x;
    if (i >= NN * F) return;
    int c = i % F;
    float v = x[i] * g_scale[c] + g_shift[c];
    if (relu) v = fmaxf(v, 0.f);
    x[i] = v;
}

// ---------------- host driver ----------------------------------------------
extern "C" void kernel_launch(void* const* d_in, const int* in_sizes, int n_in,
                              void* d_out, int out_size) {
    const float* x   = (const float*)d_in[0];
    const int*   ei  = (const int*)d_in[1];
    const int*   src = ei;
    const int*   dst = ei + EE;
    const float* W1 = (const float*)d_in[2],  *as1 = (const float*)d_in[3],
               * ad1 = (const float*)d_in[4], *b1  = (const float*)d_in[5],
               * g1  = (const float*)d_in[6], *be1 = (const float*)d_in[7];
    const float* W2 = (const float*)d_in[8],  *as2 = (const float*)d_in[9],
               * ad2 = (const float*)d_in[10], *b2  = (const float*)d_in[11],
               * g2  = (const float*)d_in[12], *be2 = (const float*)d_in[13];
    const float* W3 = (const float*)d_in[14], *as3 = (const float*)d_in[15],
               * ad3 = (const float*)d_in[16], *b3  = (const float*)d_in[17];
    const float* W4 = (const float*)d_in[18], *as4 = (const float*)d_in[19],
               * ad4 = (const float*)d_in[20], *b4  = (const float*)d_in[21],
               * g4  = (const float*)d_in[22], *be4 = (const float*)d_in[23];
    const float* W5 = (const float*)d_in[24], *as5 = (const float*)d_in[25],
               * ad5 = (const float*)d_in[26], *b5  = (const float*)d_in[27];

    float *h, *acc, *fa, *fb, *es, *ed, *den, *bns, *bnq;
    cudaGetSymbolAddress((void**)&h,   g_h);
    cudaGetSymbolAddress((void**)&acc, g_acc);
    cudaGetSymbolAddress((void**)&fa,  g_fa);
    cudaGetSymbolAddress((void**)&fb,  g_fb);
    cudaGetSymbolAddress((void**)&es,  g_es);
    cudaGetSymbolAddress((void**)&ed,  g_ed);
    cudaGetSymbolAddress((void**)&den, g_den);
    cudaGetSymbolAddress((void**)&bns, g_bnsum);
    cudaGetSymbolAddress((void**)&bnq, g_bnsq);

    const int EBLK = (EE * 32) / 256;   // 100000 blocks, one warp per edge

    auto run_gat = [&](const float* in, int Min, int F, int H, const float* Wt,
                       const float* asr, const float* adt, const float* bb,
                       float* out, bool relu) {
        dim3 gb(32, 8);
        gemm_k<<<dim3(F / 32, (NN + 31) / 32), gb>>>(in, Wt, h, Min, F);
        int D = F / H;
        attn_k<<<(NN * H + 255) / 256, 256>>>(h, asr, adt, es, ed, H, D);
        zero_k<<<(NN * H + 255) / 256, 256>>>(den, NN * H);
        zero_k<<<(NN * F + 255) / 256, 256>>>(acc, NN * F);
        if (F == 128 && H == 4)
            edge_k<128, 4><<<EBLK, 256>>>(src, dst, h, es, ed, den, acc);
        else if (F == 128)
            edge_k<128, 1><<<EBLK, 256>>>(src, dst, h, es, ed, den, acc);
        else
            edge_k<32, 1><<<EBLK, 256>>>(src, dst, h, es, ed, den, acc);
        fin_k<<<(NN * F + 255) / 256, 256>>>(h, es, ed, den, acc, bb, out, F, H,
                                             relu ? 1 : 0);
    };

    auto run_bn = [&](float* xbuf, int F, const float* g, const float* be, bool relu) {
        zero_k<<<1, 256>>>(bns, F);
        zero_k<<<1, 256>>>(bnq, F);
        bn_part<<<(NN + 127) / 128, F>>>(xbuf, F);
        bn_fin<<<1, 128>>>(g, be, F);
        bn_apply<<<(NN * F + 255) / 256, 256>>>(xbuf, F, relu ? 1 : 0);
    };

    // encoder
    run_gat(x, 128, 128, 4, W1, as1, ad1, b1, fa, true);
    run_bn(fa, 128, g1, be1, false);
    run_gat(fa, 128, 128, 4, W2, as2, ad2, b2, fb, true);
    run_bn(fb, 128, g2, be2, false);
    run_gat(fb, 128, 32, 1, W3, as3, ad3, b3, fa, true);
    // decoder
    run_gat(fa, 32, 32, 1, W4, as4, ad4, b4, fb, true);
    run_bn(fb, 32, g4, be4, true);
    run_gat(fb, 32, 128, 1, W5, as5, ad5, b5, (float*)d_out, false);
}

// round 3
// speedup vs baseline: 1.4383x; 1.4383x over previous
#include <cuda_runtime.h>

#define NN 50000
#define EE 800000
#define FMAX 128

static __constant__ float kNEG = 0.2f;
#define EPS_BN 1e-5f

// ---------------- scratch (device globals; no allocation allowed) ----------
__device__ float g_h[NN * FMAX];     // transformed features  h = in @ W
__device__ float g_fa[NN * FMAX];    // node feature ping
__device__ float g_fb[NN * FMAX];    // node feature pong
__device__ float g_es[NN * 4];
__device__ float g_ed[NN * 4];
__device__ int   g_deg[NN];
__device__ int   g_rowptr[NN + 1];
__device__ int   g_cursor[NN];
__device__ int   g_adj[EE];
__device__ float g_bnsum[FMAX];
__device__ float g_bnsq[FMAX];
__device__ float g_scale[FMAX];
__device__ float g_shift[FMAX];

// ---------------- utility ---------------------------------------------------
__global__ void zero_k(float* p, int n) {
    int i = blockIdx.x * 256 + threadIdx.x;
    if (i < n) p[i] = 0.f;
}
__global__ void zeroi_k(int* p, int n) {
    int i = blockIdx.x * 256 + threadIdx.x;
    if (i < n) p[i] = 0;
}

// ---------------- CSR build (graph is identical for all 5 layers) ----------
__global__ void hist_k(const int* __restrict__ dst, int* deg) {
    int e = blockIdx.x * 256 + threadIdx.x;
    if (e < EE) atomicAdd(&deg[dst[e]], 1);
}

// single-block exclusive scan of deg -> rowptr (+ copy to cursor)
__global__ void scan_k(const int* __restrict__ deg, int* rowptr, int* cursor) {
    const int T = 1024;
    const int C = (NN + T - 1) / T;  // 49
    __shared__ int ssum[32];
    int t = threadIdx.x;
    int base = t * C;
    int s = 0;
    for (int i = 0; i < C; i++) {
        int idx = base + i;
        if (idx < NN) s += deg[idx];
    }
    int lane = t & 31, wid = t >> 5;
    int v = s;
    for (int o = 1; o < 32; o <<= 1) {
        int u = __shfl_up_sync(0xffffffffu, v, o);
        if (lane >= o) v += u;
    }
    if (lane == 31) ssum[wid] = v;
    __syncthreads();
    if (wid == 0) {
        int w = ssum[lane];
        for (int o = 1; o < 32; o <<= 1) {
            int u = __shfl_up_sync(0xffffffffu, w, o);
            if (lane >= o) w += u;
        }
        ssum[lane] = w;
    }
    __syncthreads();
    int excl = v - s + (wid ? ssum[wid - 1] : 0);
    int run = excl;
    for (int i = 0; i < C; i++) {
        int idx = base + i;
        if (idx < NN) {
            rowptr[idx] = run;
            cursor[idx] = run;
            run += deg[idx];
        }
    }
    if (t == T - 1) rowptr[NN] = run;
}

__global__ void scatter_k(const int* __restrict__ src, const int* __restrict__ dst,
                          int* cursor, int* adj) {
    int e = blockIdx.x * 256 + threadIdx.x;
    if (e >= EE) return;
    int d = dst[e];
    int p = atomicAdd(&cursor[d], 1);
    adj[p] = src[e];
}

// ---------------- GEMM: C[N,K] = A[N,M] @ W[M,K] ---------------------------
__global__ void gemm_k(const float* __restrict__ A, const float* __restrict__ W,
                       float* __restrict__ C, int M, int K) {
    int col = blockIdx.x * 32 + threadIdx.x;
    int r0  = (blockIdx.y * 8 + threadIdx.y) * 4;
    long o0 = (long)min(r0 + 0, NN - 1) * M;
    long o1 = (long)min(r0 + 1, NN - 1) * M;
    long o2 = (long)min(r0 + 2, NN - 1) * M;
    long o3 = (long)min(r0 + 3, NN - 1) * M;
    float a0 = 0.f, a1 = 0.f, a2 = 0.f, a3 = 0.f;
#pragma unroll 4
    for (int m = 0; m < M; m++) {
        float w = W[m * K + col];
        a0 = fmaf(w, A[o0 + m], a0);
        a1 = fmaf(w, A[o1 + m], a1);
        a2 = fmaf(w, A[o2 + m], a2);
        a3 = fmaf(w, A[o3 + m], a3);
    }
    if (r0 + 0 < NN) C[(long)(r0 + 0) * K + col] = a0;
    if (r0 + 1 < NN) C[(long)(r0 + 1) * K + col] = a1;
    if (r0 + 2 < NN) C[(long)(r0 + 2) * K + col] = a2;
    if (r0 + 3 < NN) C[(long)(r0 + 3) * K + col] = a3;
}

// ---------------- attention coefficients -----------------------------------
__global__ void attn_k(const float* __restrict__ h, const float* __restrict__ asr,
                       const float* __restrict__ adt, float* __restrict__ es,
                       float* __restrict__ ed, int H, int D) {
    int i = blockIdx.x * blockDim.x + threadIdx.x;
    if (i >= NN * H) return;
    int n = i / H, hd = i - n * H;
    const float* hp = h + (long)n * H * D + hd * D;
    const float* a1 = asr + hd * D;
    const float* a2 = adt + hd * D;
    float s = 0.f, d = 0.f;
    for (int k = 0; k < D; k++) {
        float v = hp[k];
        s = fmaf(v, a1[k], s);
        d = fmaf(v, a2[k], d);
    }
    es[i] = s;
    ed[i] = d;
}

// ---------------- fused gather: softmax-agg + self-loop + bias + relu ------
// one warp per dst node; accumulators live in registers; no atomics.
template <int F, int H>
__global__ void gat_gather_k(const int* __restrict__ rowptr, const int* __restrict__ adj,
                             const float* __restrict__ h, const float* __restrict__ es,
                             const float* __restrict__ ed, const float* __restrict__ bias,
                             float* __restrict__ out, int relu) {
    constexpr int VEC = F / 32;
    constexpr int D   = F / H;
    int w = (blockIdx.x * blockDim.x + threadIdx.x) >> 5;
    if (w >= NN) return;
    int lane = threadIdx.x & 31;
    int f0   = lane * VEC;
    int head = f0 / D;
    float edn = ed[w * H + head];
    float acc0 = 0.f, acc1 = 0.f, acc2 = 0.f, acc3 = 0.f;
    float den = 0.f;
    int beg = rowptr[w], end = rowptr[w + 1];
    for (int base = beg; base < end; base += 32) {
        int cnt  = min(32, end - base);
        int sreg = (base + lane < end) ? adj[base + lane] : 0;
        for (int j = 0; j < cnt; j++) {
            int s   = __shfl_sync(0xffffffffu, sreg, j);
            float a = es[s * H + head] + edn;
            a = a > 0.f ? a : kNEG * a;
            float ex = __expf(a);
            den += ex;
            const float* hp = h + (long)s * F + f0;
            if (VEC == 4) {
                float4 hv = *(const float4*)hp;
                acc0 = fmaf(ex, hv.x, acc0);
                acc1 = fmaf(ex, hv.y, acc1);
                acc2 = fmaf(ex, hv.z, acc2);
                acc3 = fmaf(ex, hv.w, acc3);
            } else {
                acc0 = fmaf(ex, hp[0], acc0);
            }
        }
    }
    {   // self loop
        float a = es[w * H + head] + edn;
        a = a > 0.f ? a : kNEG * a;
        float ex = __expf(a);
        den += ex;
        const float* hp = h + (long)w * F + f0;
        if (VEC == 4) {
            float4 hv = *(const float4*)hp;
            acc0 = fmaf(ex, hv.x, acc0);
            acc1 = fmaf(ex, hv.y, acc1);
            acc2 = fmaf(ex, hv.z, acc2);
            acc3 = fmaf(ex, hv.w, acc3);
        } else {
            acc0 = fmaf(ex, hp[0], acc0);
        }
    }
    float inv = 1.f / den;
    float* op = out + (long)w * F + f0;
    if (VEC == 4) {
        float4 o;
        o.x = acc0 * inv + bias[f0 + 0];
        o.y = acc1 * inv + bias[f0 + 1];
        o.z = acc2 * inv + bias[f0 + 2];
        o.w = acc3 * inv + bias[f0 + 3];
        if (relu) {
            o.x = fmaxf(o.x, 0.f); o.y = fmaxf(o.y, 0.f);
            o.z = fmaxf(o.z, 0.f); o.w = fmaxf(o.w, 0.f);
        }
        *(float4*)op = o;
    } else {
        float o = acc0 * inv + bias[f0];
        if (relu) o = fmaxf(o, 0.f);
        op[0] = o;
    }
}

// ---------------- batchnorm -------------------------------------------------
__global__ void bn_part(const float* __restrict__ x, int F) {
    int c  = threadIdx.x;
    int r0 = blockIdx.x * 128;
    int r1 = min(r0 + 128, NN);
    float s = 0.f, s2 = 0.f;
    for (int r = r0; r < r1; r++) {
        float v = x[(long)r * F + c];
        s += v;
        s2 = fmaf(v, v, s2);
    }
    atomicAdd(&g_bnsum[c], s);
    atomicAdd(&g_bnsq[c], s2);
}

__global__ void bn_fin(const float* __restrict__ g, const float* __restrict__ be, int F) {
    int c = threadIdx.x;
    if (c >= F) return;
    float m   = g_bnsum[c] * (1.f / NN);
    float var = g_bnsq[c] * (1.f / NN) - m * m;
    float rs  = rsqrtf(var + EPS_BN);
    g_scale[c] = g[c] * rs;
    g_shift[c] = be[c] - m * g[c] * rs;
}

__global__ void bn_apply(float* __restrict__ x, int F, int relu) {
    int i = blockIdx.x * blockDim.x + threadIdx.x;
    if (i >= NN * F) return;
    int c = i % F;
    float v = x[i] * g_scale[c] + g_shift[c];
    if (relu) v = fmaxf(v, 0.f);
    x[i] = v;
}

// ---------------- host driver ----------------------------------------------
extern "C" void kernel_launch(void* const* d_in, const int* in_sizes, int n_in,
                              void* d_out, int out_size) {
    const float* x   = (const float*)d_in[0];
    const int*   ei  = (const int*)d_in[1];
    const int*   src = ei;
    const int*   dst = ei + EE;
    const float* W1 = (const float*)d_in[2],  *as1 = (const float*)d_in[3],
               * ad1 = (const float*)d_in[4], *b1  = (const float*)d_in[5],
               * g1  = (const float*)d_in[6], *be1 = (const float*)d_in[7];
    const float* W2 = (const float*)d_in[8],  *as2 = (const float*)d_in[9],
               * ad2 = (const float*)d_in[10], *b2  = (const float*)d_in[11],
               * g2  = (const float*)d_in[12], *be2 = (const float*)d_in[13];
    const float* W3 = (const float*)d_in[14], *as3 = (const float*)d_in[15],
               * ad3 = (const float*)d_in[16], *b3  = (const float*)d_in[17];
    const float* W4 = (const float*)d_in[18], *as4 = (const float*)d_in[19],
               * ad4 = (const float*)d_in[20], *b4  = (const float*)d_in[21],
               * g4  = (const float*)d_in[22], *be4 = (const float*)d_in[23];
    const float* W5 = (const float*)d_in[24], *as5 = (const float*)d_in[25],
               * ad5 = (const float*)d_in[26], *b5  = (const float*)d_in[27];

    float *h, *fa, *fb, *es, *ed, *bns, *bnq;
    int *deg, *rowptr, *cursor, *adj;
    cudaGetSymbolAddress((void**)&h,      g_h);
    cudaGetSymbolAddress((void**)&fa,     g_fa);
    cudaGetSymbolAddress((void**)&fb,     g_fb);
    cudaGetSymbolAddress((void**)&es,     g_es);
    cudaGetSymbolAddress((void**)&ed,     g_ed);
    cudaGetSymbolAddress((void**)&deg,    g_deg);
    cudaGetSymbolAddress((void**)&rowptr, g_rowptr);
    cudaGetSymbolAddress((void**)&cursor, g_cursor);
    cudaGetSymbolAddress((void**)&adj,    g_adj);
    cudaGetSymbolAddress((void**)&bns,    g_bnsum);
    cudaGetSymbolAddress((void**)&bnq,    g_bnsq);

    // ---- CSR build (once; graph shared by all 5 layers) ----
    zeroi_k<<<(NN + 255) / 256, 256>>>(deg, NN);
    hist_k<<<(EE + 255) / 256, 256>>>(dst, deg);
    scan_k<<<1, 1024>>>(deg, rowptr, cursor);
    scatter_k<<<(EE + 255) / 256, 256>>>(src, dst, cursor, adj);

    const int GBLK = (NN * 32 + 255) / 256;   // warp per node

    auto run_gat = [&](const float* in, int Min, int F, int H, const float* Wt,
                       const float* asr, const float* adt, const float* bb,
                       float* out, bool relu) {
        dim3 gb(32, 8);
        gemm_k<<<dim3(F / 32, (NN + 31) / 32), gb>>>(in, Wt, h, Min, F);
        int D = F / H;
        attn_k<<<(NN * H + 255) / 256, 256>>>(h, asr, adt, es, ed, H, D);
        if (F == 128 && H == 4)
            gat_gather_k<128, 4><<<GBLK, 256>>>(rowptr, adj, h, es, ed, bb, out, relu);
        else if (F == 128)
            gat_gather_k<128, 1><<<GBLK, 256>>>(rowptr, adj, h, es, ed, bb, out, relu);
        else
            gat_gather_k<32, 1><<<GBLK, 256>>>(rowptr, adj, h, es, ed, bb, out, relu);
    };

    auto run_bn = [&](float* xbuf, int F, const float* g, const float* be, bool relu) {
        zero_k<<<1, 256>>>(bns, F);
        zero_k<<<1, 256>>>(bnq, F);
        bn_part<<<(NN + 127) / 128, F>>>(xbuf, F);
        bn_fin<<<1, 128>>>(g, be, F);
        bn_apply<<<(NN * F + 255) / 256, 256>>>(xbuf, F, relu ? 1 : 0);
    };

    // encoder
    run_gat(x, 128, 128, 4, W1, as1, ad1, b1, fa, true);
    run_bn(fa, 128, g1, be1, false);
    run_gat(fa, 128, 128, 4, W2, as2, ad2, b2, fb, true);
    run_bn(fb, 128, g2, be2, false);
    run_gat(fb, 128, 32, 1, W3, as3, ad3, b3, fa, true);
    // decoder
    run_gat(fa, 32, 32, 1, W4, as4, ad4, b4, fb, true);
    run_bn(fb, 32, g4, be4, true);
    run_gat(fb, 32, 128, 1, W5, as5, ad5, b5, (float*)d_out, false);
}

// round 4
// speedup vs baseline: 2.2930x; 1.5943x over previous
#include <cuda_runtime.h>

#define NN 50000
#define EE 800000
#define FMAX 128

static __constant__ float kNEG = 0.2f;
#define EPS_BN 1e-5f

// ---------------- scratch (device globals; no allocation allowed) ----------
__device__ float g_h[NN * FMAX];     // transformed features  h = in @ W
__device__ float g_fa[NN * FMAX];    // node feature ping
__device__ float g_fb[NN * FMAX];    // node feature pong
__device__ float g_es[NN * 4];
__device__ float g_ed[NN * 4];
__device__ int   g_deg[NN];
__device__ int   g_rowptr[NN + 1];
__device__ int   g_cursor[NN];
__device__ int   g_adj[EE];
__device__ float g_bnstat[2 * FMAX];   // [0,F) sum, [FMAX,FMAX+F) sumsq
__device__ float g_Wf[FMAX * FMAX];    // BN-folded weight
__device__ float g_rvec[FMAX];         // BN-folded bias row

// ---------------- utility ---------------------------------------------------
__global__ void zero_k(float* p, int n) {
    int i = blockIdx.x * 256 + threadIdx.x;
    if (i < n) p[i] = 0.f;
}
__global__ void zeroi_k(int* p, int n) {
    int i = blockIdx.x * 256 + threadIdx.x;
    if (i < n) p[i] = 0;
}

// ---------------- CSR build (graph identical for all 5 layers) -------------
__global__ void hist_k(const int* __restrict__ dst, int* deg) {
    int e = blockIdx.x * 256 + threadIdx.x;
    if (e < EE) atomicAdd(&deg[dst[e]], 1);
}

__global__ void scan_k(const int* __restrict__ deg, int* rowptr, int* cursor) {
    const int T = 1024;
    const int C = (NN + T - 1) / T;
    __shared__ int ssum[32];
    int t = threadIdx.x;
    int base = t * C;
    int s = 0;
    for (int i = 0; i < C; i++) {
        int idx = base + i;
        if (idx < NN) s += deg[idx];
    }
    int lane = t & 31, wid = t >> 5;
    int v = s;
    for (int o = 1; o < 32; o <<= 1) {
        int u = __shfl_up_sync(0xffffffffu, v, o);
        if (lane >= o) v += u;
    }
    if (lane == 31) ssum[wid] = v;
    __syncthreads();
    if (wid == 0) {
        int w = ssum[lane];
        for (int o = 1; o < 32; o <<= 1) {
            int u = __shfl_up_sync(0xffffffffu, w, o);
            if (lane >= o) w += u;
        }
        ssum[lane] = w;
    }
    __syncthreads();
    int excl = v - s + (wid ? ssum[wid - 1] : 0);
    int run = excl;
    for (int i = 0; i < C; i++) {
        int idx = base + i;
        if (idx < NN) {
            rowptr[idx] = run;
            cursor[idx] = run;
            run += deg[idx];
        }
    }
    if (t == T - 1) rowptr[NN] = run;
}

__global__ void scatter_k(const int* __restrict__ src, const int* __restrict__ dst,
                          int* cursor, int* adj) {
    int e = blockIdx.x * 256 + threadIdx.x;
    if (e >= EE) return;
    int d = dst[e];
    int p = atomicAdd(&cursor[d], 1);
    adj[p] = src[e];
}

// ---------------- fused GEMM + attention epilogue ---------------------------
// C[N,K] = A[N,M] @ W[M,K] (+ rvec);  es/ed[n,h] = C[n,h,:] . a_{s,d}[h,:]
// block (32,8): thread = 4 rows x CPT cols. m-vectorized float4 loads.
template <int M, int K, int H>
__global__ void __launch_bounds__(256)
gemm2_k(const float* __restrict__ A, const float* __restrict__ W,
        const float* __restrict__ rvec,
        const float* __restrict__ avs, const float* __restrict__ avd,
        float* __restrict__ C, float* __restrict__ es, float* __restrict__ ed) {
    constexpr int CPT = (K == 128) ? 4 : 1;
    constexpr int D   = K / H;
    constexpr int G   = D / CPT;        // lanes per head group (8 or 32)
    int tx = threadIdx.x, ty = threadIdx.y;
    int r0 = blockIdx.y * 32 + ty * 4;
    int c0 = tx * CPT;

    long ab[4];
#pragma unroll
    for (int r = 0; r < 4; r++) ab[r] = (long)min(r0 + r, NN - 1) * M;

    float acc[4][CPT];
#pragma unroll
    for (int r = 0; r < 4; r++)
#pragma unroll
        for (int c = 0; c < CPT; c++) acc[r][c] = 0.f;

#pragma unroll 2
    for (int m = 0; m < M; m += 4) {
        float4 av[4];
#pragma unroll
        for (int r = 0; r < 4; r++) av[r] = *(const float4*)&A[ab[r] + m];
#pragma unroll
        for (int mi = 0; mi < 4; mi++) {
            float wq[CPT];
            if (CPT == 4) {
                float4 t = *(const float4*)&W[(m + mi) * K + c0];
                wq[0] = t.x; wq[1] = t.y; wq[2] = t.z; wq[3] = t.w;
            } else {
                wq[0] = W[(m + mi) * K + c0];
            }
#pragma unroll
            for (int r = 0; r < 4; r++) {
                float am = ((const float*)&av[r])[mi];
#pragma unroll
                for (int c = 0; c < CPT; c++)
                    acc[r][c] = fmaf(am, wq[c], acc[r][c]);
            }
        }
    }

    float rv[CPT], ws[CPT], wd[CPT];
#pragma unroll
    for (int c = 0; c < CPT; c++) {
        rv[c] = rvec ? rvec[c0 + c] : 0.f;
        ws[c] = avs[c0 + c];
        wd[c] = avd[c0 + c];
    }

#pragma unroll
    for (int r = 0; r < 4; r++) {
        float hv[CPT];
        float pes = 0.f, ped = 0.f;
#pragma unroll
        for (int c = 0; c < CPT; c++) {
            hv[c] = acc[r][c] + rv[c];
            pes = fmaf(hv[c], ws[c], pes);
            ped = fmaf(hv[c], wd[c], ped);
        }
        int row = r0 + r;
        if (row < NN) {
            if (CPT == 4)
                *(float4*)&C[(long)row * K + c0] =
                    make_float4(hv[0], hv[1], hv[2], hv[3]);
            else
                C[(long)row * K + c0] = hv[0];
        }
#pragma unroll
        for (int o = G / 2; o > 0; o >>= 1) {
            pes += __shfl_xor_sync(0xffffffffu, pes, o);
            ped += __shfl_xor_sync(0xffffffffu, ped, o);
        }
        if ((tx % G) == 0 && row < NN) {
            int head = c0 / D;
            es[row * H + head] = pes;
            ed[row * H + head] = ped;
        }
    }
}

// ---------------- fused gather: softmax-agg + self-loop + bias + relu ------
template <int F, int H>
__global__ void gat_gather_k(const int* __restrict__ rowptr, const int* __restrict__ adj,
                             const float* __restrict__ h, const float* __restrict__ es,
                             const float* __restrict__ ed, const float* __restrict__ bias,
                             float* __restrict__ out, int relu) {
    constexpr int VEC = F / 32;
    constexpr int D   = F / H;
    int w = (blockIdx.x * blockDim.x + threadIdx.x) >> 5;
    if (w >= NN) return;
    int lane = threadIdx.x & 31;
    int f0   = lane * VEC;
    int head = f0 / D;
    float edn = ed[w * H + head];
    float acc0 = 0.f, acc1 = 0.f, acc2 = 0.f, acc3 = 0.f;
    float den = 0.f;
    int beg = rowptr[w], end = rowptr[w + 1];
    for (int base = beg; base < end; base += 32) {
        int cnt  = min(32, end - base);
        int sreg = (base + lane < end) ? adj[base + lane] : 0;
#pragma unroll 4
        for (int j = 0; j < cnt; j++) {
            int s   = __shfl_sync(0xffffffffu, sreg, j);
            float a = es[s * H + head] + edn;
            a = a > 0.f ? a : kNEG * a;
            float ex = __expf(a);
            den += ex;
            const float* hp = h + (long)s * F + f0;
            if (VEC == 4) {
                float4 hv = *(const float4*)hp;
                acc0 = fmaf(ex, hv.x, acc0);
                acc1 = fmaf(ex, hv.y, acc1);
                acc2 = fmaf(ex, hv.z, acc2);
                acc3 = fmaf(ex, hv.w, acc3);
            } else {
                acc0 = fmaf(ex, hp[0], acc0);
            }
        }
    }
    {   // self loop
        float a = es[w * H + head] + edn;
        a = a > 0.f ? a : kNEG * a;
        float ex = __expf(a);
        den += ex;
        const float* hp = h + (long)w * F + f0;
        if (VEC == 4) {
            float4 hv = *(const float4*)hp;
            acc0 = fmaf(ex, hv.x, acc0);
            acc1 = fmaf(ex, hv.y, acc1);
            acc2 = fmaf(ex, hv.z, acc2);
            acc3 = fmaf(ex, hv.w, acc3);
        } else {
            acc0 = fmaf(ex, hp[0], acc0);
        }
    }
    float inv = 1.f / den;
    float* op = out + (long)w * F + f0;
    if (VEC == 4) {
        float4 o;
        o.x = acc0 * inv + bias[f0 + 0];
        o.y = acc1 * inv + bias[f0 + 1];
        o.z = acc2 * inv + bias[f0 + 2];
        o.w = acc3 * inv + bias[f0 + 3];
        if (relu) {
            o.x = fmaxf(o.x, 0.f); o.y = fmaxf(o.y, 0.f);
            o.z = fmaxf(o.z, 0.f); o.w = fmaxf(o.w, 0.f);
        }
        *(float4*)op = o;
    } else {
        float o = acc0 * inv + bias[f0];
        if (relu) o = fmaxf(o, 0.f);
        op[0] = o;
    }
}

// ---------------- batchnorm stats -------------------------------------------
__global__ void bn_part(const float* __restrict__ x, int F) {
    int t = threadIdx.x;                 // 128 threads
    int c = t % F;
    int sub = t / F;
    int step = 128 / F;
    int r0 = blockIdx.x * 128;
    int r1 = min(r0 + 128, NN);
    float s = 0.f, s2 = 0.f;
    for (int r = r0 + sub; r < r1; r += step) {
        float v = x[(long)r * F + c];
        s += v;
        s2 = fmaf(v, v, s2);
    }
    atomicAdd(&g_bnstat[c], s);
    atomicAdd(&g_bnstat[FMAX + c], s2);
}

// ---- fold BN into next layer's weight: W'[m,k]=sc[m]W[m,k]; rvec[k]=sum sh[m]W[m,k]
__global__ void fold_k(const float* __restrict__ g, const float* __restrict__ be,
                       const float* __restrict__ W, float* __restrict__ Wout,
                       float* __restrict__ rvec, int M, int K) {
    __shared__ float sc[FMAX], sh[FMAX];
    int t = threadIdx.x;                 // 128 threads
    if (t < M) {
        float mu  = g_bnstat[t] * (1.f / NN);
        float var = g_bnstat[FMAX + t] * (1.f / NN) - mu * mu;
        float rs  = rsqrtf(var + EPS_BN);
        sc[t] = g[t] * rs;
        sh[t] = be[t] - mu * g[t] * rs;
    }
    __syncthreads();
    if (t < K) {
        float rv = 0.f;
        for (int m = 0; m < M; m++) {
            float w = W[m * K + t];
            Wout[m * K + t] = w * sc[m];
            rv = fmaf(sh[m], w, rv);
        }
        rvec[t] = rv;
    }
}

// ---- standalone BN apply (+relu) for the decoder BN ------------------------
__global__ void bn_apply2(float* __restrict__ x, const float* __restrict__ g,
                          const float* __restrict__ be, int F, int relu) {
    __shared__ float sc[FMAX], sh[FMAX];
    int t = threadIdx.x;
    if (t < F) {
        float mu  = g_bnstat[t] * (1.f / NN);
        float var = g_bnstat[FMAX + t] * (1.f / NN) - mu * mu;
        float rs  = rsqrtf(var + EPS_BN);
        sc[t] = g[t] * rs;
        sh[t] = be[t] - mu * g[t] * rs;
    }
    __syncthreads();
    int total = NN * F;
    for (int i = blockIdx.x * 256 + t; i < total; i += gridDim.x * 256) {
        int c = i & (F - 1);
        float v = x[i] * sc[c] + sh[c];
        if (relu) v = fmaxf(v, 0.f);
        x[i] = v;
    }
}

// ---------------- host driver ----------------------------------------------
extern "C" void kernel_launch(void* const* d_in, const int* in_sizes, int n_in,
                              void* d_out, int out_size) {
    const float* x   = (const float*)d_in[0];
    const int*   ei  = (const int*)d_in[1];
    const int*   src = ei;
    const int*   dst = ei + EE;
    const float* W1 = (const float*)d_in[2],  *as1 = (const float*)d_in[3],
               * ad1 = (const float*)d_in[4], *b1  = (const float*)d_in[5],
               * g1  = (const float*)d_in[6], *be1 = (const float*)d_in[7];
    const float* W2 = (const float*)d_in[8],  *as2 = (const float*)d_in[9],
               * ad2 = (const float*)d_in[10], *b2  = (const float*)d_in[11],
               * g2  = (const float*)d_in[12], *be2 = (const float*)d_in[13];
    const float* W3 = (const float*)d_in[14], *as3 = (const float*)d_in[15],
               * ad3 = (const float*)d_in[16], *b3  = (const float*)d_in[17];
    const float* W4 = (const float*)d_in[18], *as4 = (const float*)d_in[19],
               * ad4 = (const float*)d_in[20], *b4  = (const float*)d_in[21],
               * g4  = (const float*)d_in[22], *be4 = (const float*)d_in[23];
    const float* W5 = (const float*)d_in[24], *as5 = (const float*)d_in[25],
               * ad5 = (const float*)d_in[26], *b5  = (const float*)d_in[27];

    float *h, *fa, *fb, *es, *ed, *bns, *Wf, *rv;
    int *deg, *rowptr, *cursor, *adj;
    cudaGetSymbolAddress((void**)&h,      g_h);
    cudaGetSymbolAddress((void**)&fa,     g_fa);
    cudaGetSymbolAddress((void**)&fb,     g_fb);
    cudaGetSymbolAddress((void**)&es,     g_es);
    cudaGetSymbolAddress((void**)&ed,     g_ed);
    cudaGetSymbolAddress((void**)&deg,    g_deg);
    cudaGetSymbolAddress((void**)&rowptr, g_rowptr);
    cudaGetSymbolAddress((void**)&cursor, g_cursor);
    cudaGetSymbolAddress((void**)&adj,    g_adj);
    cudaGetSymbolAddress((void**)&bns,    g_bnstat);
    cudaGetSymbolAddress((void**)&Wf,     g_Wf);
    cudaGetSymbolAddress((void**)&rv,     g_rvec);

    // ---- CSR build ----
    zeroi_k<<<(NN + 255) / 256, 256>>>(deg, NN);
    hist_k<<<(EE + 255) / 256, 256>>>(dst, deg);
    scan_k<<<1, 1024>>>(deg, rowptr, cursor);
    scatter_k<<<(EE + 255) / 256, 256>>>(src, dst, cursor, adj);

    const dim3 GB(32, 8);
    const dim3 GG(1, (NN + 31) / 32);
    const int  GBLK = (NN * 32 + 255) / 256;

    // ---- L1: GAT(128 -> 128, H=4) ----
    gemm2_k<128, 128, 4><<<GG, GB>>>(x, W1, nullptr, as1, ad1, h, es, ed);
    gat_gather_k<128, 4><<<GBLK, 256>>>(rowptr, adj, h, es, ed, b1, fa, 1);

    // ---- BN1 (folded into L2 gemm) ----
    zero_k<<<1, 256>>>(bns, 2 * FMAX);
    bn_part<<<(NN + 127) / 128, 128>>>(fa, 128);
    fold_k<<<1, 128>>>(g1, be1, W2, Wf, rv, 128, 128);

    // ---- L2: GAT(128 -> 128, H=4) ----
    gemm2_k<128, 128, 4><<<GG, GB>>>(fa, Wf, rv, as2, ad2, h, es, ed);
    gat_gather_k<128, 4><<<GBLK, 256>>>(rowptr, adj, h, es, ed, b2, fb, 1);

    // ---- BN2 (folded into L3 gemm) ----
    zero_k<<<1, 256>>>(bns, 2 * FMAX);
    bn_part<<<(NN + 127) / 128, 128>>>(fb, 128);
    fold_k<<<1, 128>>>(g2, be2, W3, Wf, rv, 128, 32);

    // ---- L3: GAT(128 -> 32, H=1) ----
    gemm2_k<128, 32, 1><<<GG, GB>>>(fb, Wf, rv, as3, ad3, h, es, ed);
    gat_gather_k<32, 1><<<GBLK, 256>>>(rowptr, adj, h, es, ed, b3, fa, 1);

    // ---- L4: GAT(32 -> 32, H=1) ----
    gemm2_k<32, 32, 1><<<GG, GB>>>(fa, W4, nullptr, as4, ad4, h, es, ed);
    gat_gather_k<32, 1><<<GBLK, 256>>>(rowptr, adj, h, es, ed, b4, fb, 1);

    // ---- BN4 + relu ----
    zero_k<<<1, 256>>>(bns, 2 * FMAX);
    bn_part<<<(NN + 127) / 128, 128>>>(fb, 32);
    bn_apply2<<<256, 256>>>(fb, g4, be4, 32, 1);

    // ---- L5: GAT(32 -> 128, H=1) ----
    gemm2_k<32, 128, 1><<<GG, GB>>>(fb, W5, nullptr, as5, ad5, h, es, ed);
    gat_gather_k<128, 1><<<GBLK, 256>>>(rowptr, adj, h, es, ed, b5, (float*)d_out, 0);
}

// round 5
// speedup vs baseline: 2.3002x; 1.0031x over previous
#include <cuda_runtime.h>
#include <cuda_fp16.h>

#define NN 50000
#define EE 800000
#define FMAX 128

static __constant__ float kNEG = 0.2f;
#define EPS_BN 1e-5f

// ---------------- scratch (device globals; no allocation allowed) ----------
__device__ __half g_hh[NN * FMAX];   // transformed features (fp16), gather input
__device__ float g_fa[NN * FMAX];    // node feature ping
__device__ float g_fb[NN * FMAX];    // node feature pong
__device__ float g_es[NN * 4];
__device__ float g_ed[NN * 4];
__device__ int   g_deg[NN];
__device__ int   g_rowptr[NN + 1];
__device__ int   g_cursor[NN];
__device__ int   g_adj[EE];
__device__ float g_bnstat[2 * FMAX];   // [0,F) sum, [FMAX,FMAX+F) sumsq
__device__ float g_Wf[FMAX * FMAX];    // BN-folded weight
__device__ float g_rvec[FMAX];         // BN-folded bias row

// ---------------- utility ---------------------------------------------------
__global__ void zero_k(float* p, int n) {
    int i = blockIdx.x * 256 + threadIdx.x;
    if (i < n) p[i] = 0.f;
}
__global__ void zeroi_k(int* p, int n) {
    int i = blockIdx.x * 256 + threadIdx.x;
    if (i < n) p[i] = 0;
}

// ---------------- CSR build (graph identical for all 5 layers) -------------
__global__ void hist_k(const int* __restrict__ dst, int* deg) {
    int e = blockIdx.x * 256 + threadIdx.x;
    if (e < EE) atomicAdd(&deg[dst[e]], 1);
}

__global__ void scan_k(const int* __restrict__ deg, int* rowptr, int* cursor) {
    const int T = 1024;
    const int C = (NN + T - 1) / T;
    __shared__ int ssum[32];
    int t = threadIdx.x;
    int base = t * C;
    int s = 0;
    for (int i = 0; i < C; i++) {
        int idx = base + i;
        if (idx < NN) s += deg[idx];
    }
    int lane = t & 31, wid = t >> 5;
    int v = s;
    for (int o = 1; o < 32; o <<= 1) {
        int u = __shfl_up_sync(0xffffffffu, v, o);
        if (lane >= o) v += u;
    }
    if (lane == 31) ssum[wid] = v;
    __syncthreads();
    if (wid == 0) {
        int w = ssum[lane];
        for (int o = 1; o < 32; o <<= 1) {
            int u = __shfl_up_sync(0xffffffffu, w, o);
            if (lane >= o) w += u;
        }
        ssum[lane] = w;
    }
    __syncthreads();
    int excl = v - s + (wid ? ssum[wid - 1] : 0);
    int run = excl;
    for (int i = 0; i < C; i++) {
        int idx = base + i;
        if (idx < NN) {
            rowptr[idx] = run;
            cursor[idx] = run;
            run += deg[idx];
        }
    }
    if (t == T - 1) rowptr[NN] = run;
}

__global__ void scatter_k(const int* __restrict__ src, const int* __restrict__ dst,
                          int* cursor, int* adj) {
    int e = blockIdx.x * 256 + threadIdx.x;
    if (e >= EE) return;
    int d = dst[e];
    int p = atomicAdd(&cursor[d], 1);
    adj[p] = src[e];
}

// ---------------- fused GEMM + attention epilogue ---------------------------
// hh[N,K] = half(A[N,M] @ W[M,K] + rvec);  es/ed[n,h] = h[n,h,:] . a_{s,d}[h,:]
template <int M, int K, int H>
__global__ void __launch_bounds__(256)
gemm2_k(const float* __restrict__ A, const float* __restrict__ W,
        const float* __restrict__ rvec,
        const float* __restrict__ avs, const float* __restrict__ avd,
        __half* __restrict__ hh, float* __restrict__ es, float* __restrict__ ed) {
    constexpr int CPT = (K == 128) ? 4 : 1;
    constexpr int D   = K / H;
    constexpr int G   = D / CPT;        // lanes per head group (8 or 32)
    int tx = threadIdx.x, ty = threadIdx.y;
    int r0 = blockIdx.y * 32 + ty * 4;
    int c0 = tx * CPT;

    long ab[4];
#pragma unroll
    for (int r = 0; r < 4; r++) ab[r] = (long)min(r0 + r, NN - 1) * M;

    float acc[4][CPT];
#pragma unroll
    for (int r = 0; r < 4; r++)
#pragma unroll
        for (int c = 0; c < CPT; c++) acc[r][c] = 0.f;

#pragma unroll 2
    for (int m = 0; m < M; m += 4) {
        float4 av[4];
#pragma unroll
        for (int r = 0; r < 4; r++) av[r] = *(const float4*)&A[ab[r] + m];
#pragma unroll
        for (int mi = 0; mi < 4; mi++) {
            float wq[CPT];
            if (CPT == 4) {
                float4 t = *(const float4*)&W[(m + mi) * K + c0];
                wq[0] = t.x; wq[1] = t.y; wq[2] = t.z; wq[3] = t.w;
            } else {
                wq[0] = W[(m + mi) * K + c0];
            }
#pragma unroll
            for (int r = 0; r < 4; r++) {
                float am = ((const float*)&av[r])[mi];
#pragma unroll
                for (int c = 0; c < CPT; c++)
                    acc[r][c] = fmaf(am, wq[c], acc[r][c]);
            }
        }
    }

    float rv[CPT], ws[CPT], wd[CPT];
#pragma unroll
    for (int c = 0; c < CPT; c++) {
        rv[c] = rvec ? rvec[c0 + c] : 0.f;
        ws[c] = avs[c0 + c];
        wd[c] = avd[c0 + c];
    }

#pragma unroll
    for (int r = 0; r < 4; r++) {
        float hv[CPT];
        float pes = 0.f, ped = 0.f;
#pragma unroll
        for (int c = 0; c < CPT; c++) {
            hv[c] = acc[r][c] + rv[c];
            pes = fmaf(hv[c], ws[c], pes);
            ped = fmaf(hv[c], wd[c], ped);
        }
        int row = r0 + r;
        if (row < NN) {
            if (CPT == 4) {
                __half2 p0 = __floats2half2_rn(hv[0], hv[1]);
                __half2 p1 = __floats2half2_rn(hv[2], hv[3]);
                uint2 pk;
                pk.x = *(unsigned*)&p0;
                pk.y = *(unsigned*)&p1;
                *(uint2*)&hh[(long)row * K + c0] = pk;
            } else {
                hh[(long)row * K + c0] = __float2half_rn(hv[0]);
            }
        }
#pragma unroll
        for (int o = G / 2; o > 0; o >>= 1) {
            pes += __shfl_xor_sync(0xffffffffu, pes, o);
            ped += __shfl_xor_sync(0xffffffffu, ped, o);
        }
        if ((tx % G) == 0 && row < NN) {
            int head = c0 / D;
            es[row * H + head] = pes;
            ed[row * H + head] = ped;
        }
    }
}

// ---------------- fused gather: softmax-agg + self-loop + bias + relu ------
// one warp per dst node; accumulators in registers; fp16 feature rows.
template <int F, int H>
__global__ void gat_gather_k(const int* __restrict__ rowptr, const int* __restrict__ adj,
                             const __half* __restrict__ hh, const float* __restrict__ es,
                             const float* __restrict__ ed, const float* __restrict__ bias,
                             float* __restrict__ out, int relu) {
    constexpr int VEC = F / 32;
    constexpr int D   = F / H;
    int w = (blockIdx.x * blockDim.x + threadIdx.x) >> 5;
    if (w >= NN) return;
    int lane = threadIdx.x & 31;
    int f0   = lane * VEC;
    int head = f0 / D;
    float edn = ed[w * H + head];
    float acc0 = 0.f, acc1 = 0.f, acc2 = 0.f, acc3 = 0.f;
    float den = 0.f;
    int beg = rowptr[w], end = rowptr[w + 1];
    for (int base = beg; base < end; base += 32) {
        int cnt  = min(32, end - base);
        int sreg = (base + lane < end) ? adj[base + lane] : 0;
#pragma unroll 8
        for (int j = 0; j < cnt; j++) {
            int s   = __shfl_sync(0xffffffffu, sreg, j);
            float a = es[s * H + head] + edn;
            a = a > 0.f ? a : kNEG * a;
            float ex = __expf(a);
            den += ex;
            const __half* hp = hh + (long)s * F + f0;
            if (VEC == 4) {
                uint2 raw = *(const uint2*)hp;
                float2 f01 = __half22float2(*(__half2*)&raw.x);
                float2 f23 = __half22float2(*(__half2*)&raw.y);
                acc0 = fmaf(ex, f01.x, acc0);
                acc1 = fmaf(ex, f01.y, acc1);
                acc2 = fmaf(ex, f23.x, acc2);
                acc3 = fmaf(ex, f23.y, acc3);
            } else {
                acc0 = fmaf(ex, __half2float(hp[0]), acc0);
            }
        }
    }
    {   // self loop
        float a = es[w * H + head] + edn;
        a = a > 0.f ? a : kNEG * a;
        float ex = __expf(a);
        den += ex;
        const __half* hp = hh + (long)w * F + f0;
        if (VEC == 4) {
            uint2 raw = *(const uint2*)hp;
            float2 f01 = __half22float2(*(__half2*)&raw.x);
            float2 f23 = __half22float2(*(__half2*)&raw.y);
            acc0 = fmaf(ex, f01.x, acc0);
            acc1 = fmaf(ex, f01.y, acc1);
            acc2 = fmaf(ex, f23.x, acc2);
            acc3 = fmaf(ex, f23.y, acc3);
        } else {
            acc0 = fmaf(ex, __half2float(hp[0]), acc0);
        }
    }
    float inv = 1.f / den;
    float* op = out + (long)w * F + f0;
    if (VEC == 4) {
        float4 o;
        o.x = acc0 * inv + bias[f0 + 0];
        o.y = acc1 * inv + bias[f0 + 1];
        o.z = acc2 * inv + bias[f0 + 2];
        o.w = acc3 * inv + bias[f0 + 3];
        if (relu) {
            o.x = fmaxf(o.x, 0.f); o.y = fmaxf(o.y, 0.f);
            o.z = fmaxf(o.z, 0.f); o.w = fmaxf(o.w, 0.f);
        }
        *(float4*)op = o;
    } else {
        float o = acc0 * inv + bias[f0];
        if (relu) o = fmaxf(o, 0.f);
        op[0] = o;
    }
}

// ---------------- batchnorm stats -------------------------------------------
__global__ void bn_part(const float* __restrict__ x, int F) {
    int t = threadIdx.x;                 // 128 threads
    int c = t % F;
    int sub = t / F;
    int step = 128 / F;
    int r0 = blockIdx.x * 128;
    int r1 = min(r0 + 128, NN);
    float s = 0.f, s2 = 0.f;
    for (int r = r0 + sub; r < r1; r += step) {
        float v = x[(long)r * F + c];
        s += v;
        s2 = fmaf(v, v, s2);
    }
    atomicAdd(&g_bnstat[c], s);
    atomicAdd(&g_bnstat[FMAX + c], s2);
}

// ---- fold BN into next layer's weight --------------------------------------
__global__ void fold_k(const float* __restrict__ g, const float* __restrict__ be,
                       const float* __restrict__ W, float* __restrict__ Wout,
                       float* __restrict__ rvec, int M, int K) {
    __shared__ float sc[FMAX], sh[FMAX];
    int t = threadIdx.x;                 // 128 threads
    if (t < M) {
        float mu  = g_bnstat[t] * (1.f / NN);
        float var = g_bnstat[FMAX + t] * (1.f / NN) - mu * mu;
        float rs  = rsqrtf(var + EPS_BN);
        sc[t] = g[t] * rs;
        sh[t] = be[t] - mu * g[t] * rs;
    }
    __syncthreads();
    if (t < K) {
        float rv = 0.f;
        for (int m = 0; m < M; m++) {
            float w = W[m * K + t];
            Wout[m * K + t] = w * sc[m];
            rv = fmaf(sh[m], w, rv);
        }
        rvec[t] = rv;
    }
}

// ---- standalone BN apply (+relu) for the decoder BN ------------------------
__global__ void bn_apply2(float* __restrict__ x, const float* __restrict__ g,
                          const float* __restrict__ be, int F, int relu) {
    __shared__ float sc[FMAX], sh[FMAX];
    int t = threadIdx.x;
    if (t < F) {
        float mu  = g_bnstat[t] * (1.f / NN);
        float var = g_bnstat[FMAX + t] * (1.f / NN) - mu * mu;
        float rs  = rsqrtf(var + EPS_BN);
        sc[t] = g[t] * rs;
        sh[t] = be[t] - mu * g[t] * rs;
    }
    __syncthreads();
    int total = NN * F;
    for (int i = blockIdx.x * 256 + t; i < total; i += gridDim.x * 256) {
        int c = i & (F - 1);
        float v = x[i] * sc[c] + sh[c];
        if (relu) v = fmaxf(v, 0.f);
        x[i] = v;
    }
}

// ---------------- host driver ----------------------------------------------
extern "C" void kernel_launch(void* const* d_in, const int* in_sizes, int n_in,
                              void* d_out, int out_size) {
    const float* x   = (const float*)d_in[0];
    const int*   ei  = (const int*)d_in[1];
    const int*   src = ei;
    const int*   dst = ei + EE;
    const float* W1 = (const float*)d_in[2],  *as1 = (const float*)d_in[3],
               * ad1 = (const float*)d_in[4], *b1  = (const float*)d_in[5],
               * g1  = (const float*)d_in[6], *be1 = (const float*)d_in[7];
    const float* W2 = (const float*)d_in[8],  *as2 = (const float*)d_in[9],
               * ad2 = (const float*)d_in[10], *b2  = (const float*)d_in[11],
               * g2  = (const float*)d_in[12], *be2 = (const float*)d_in[13];
    const float* W3 = (const float*)d_in[14], *as3 = (const float*)d_in[15],
               * ad3 = (const float*)d_in[16], *b3  = (const float*)d_in[17];
    const float* W4 = (const float*)d_in[18], *as4 = (const float*)d_in[19],
               * ad4 = (const float*)d_in[20], *b4  = (const float*)d_in[21],
               * g4  = (const float*)d_in[22], *be4 = (const float*)d_in[23];
    const float* W5 = (const float*)d_in[24], *as5 = (const float*)d_in[25],
               * ad5 = (const float*)d_in[26], *b5  = (const float*)d_in[27];

    float *fa, *fb, *es, *ed, *bns, *Wf, *rv;
    __half* hh;
    int *deg, *rowptr, *cursor, *adj;
    cudaGetSymbolAddress((void**)&hh,     g_hh);
    cudaGetSymbolAddress((void**)&fa,     g_fa);
    cudaGetSymbolAddress((void**)&fb,     g_fb);
    cudaGetSymbolAddress((void**)&es,     g_es);
    cudaGetSymbolAddress((void**)&ed,     g_ed);
    cudaGetSymbolAddress((void**)&deg,    g_deg);
    cudaGetSymbolAddress((void**)&rowptr, g_rowptr);
    cudaGetSymbolAddress((void**)&cursor, g_cursor);
    cudaGetSymbolAddress((void**)&adj,    g_adj);
    cudaGetSymbolAddress((void**)&bns,    g_bnstat);
    cudaGetSymbolAddress((void**)&Wf,     g_Wf);
    cudaGetSymbolAddress((void**)&rv,     g_rvec);

    // ---- CSR build ----
    zeroi_k<<<(NN + 255) / 256, 256>>>(deg, NN);
    hist_k<<<(EE + 255) / 256, 256>>>(dst, deg);
    scan_k<<<1, 1024>>>(deg, rowptr, cursor);
    scatter_k<<<(EE + 255) / 256, 256>>>(src, dst, cursor, adj);

    const dim3 GB(32, 8);
    const dim3 GG(1, (NN + 31) / 32);
    const int  GBLK = (NN * 32 + 255) / 256;

    // ---- L1: GAT(128 -> 128, H=4) ----
    gemm2_k<128, 128, 4><<<GG, GB>>>(x, W1, nullptr, as1, ad1, hh, es, ed);
    gat_gather_k<128, 4><<<GBLK, 256>>>(rowptr, adj, hh, es, ed, b1, fa, 1);

    // ---- BN1 (folded into L2 gemm) ----
    zero_k<<<1, 256>>>(bns, 2 * FMAX);
    bn_part<<<(NN + 127) / 128, 128>>>(fa, 128);
    fold_k<<<1, 128>>>(g1, be1, W2, Wf, rv, 128, 128);

    // ---- L2: GAT(128 -> 128, H=4) ----
    gemm2_k<128, 128, 4><<<GG, GB>>>(fa, Wf, rv, as2, ad2, hh, es, ed);
    gat_gather_k<128, 4><<<GBLK, 256>>>(rowptr, adj, hh, es, ed, b2, fb, 1);

    // ---- BN2 (folded into L3 gemm) ----
    zero_k<<<1, 256>>>(bns, 2 * FMAX);
    bn_part<<<(NN + 127) / 128, 128>>>(fb, 128);
    fold_k<<<1, 128>>>(g2, be2, W3, Wf, rv, 128, 32);

    // ---- L3: GAT(128 -> 32, H=1) ----
    gemm2_k<128, 32, 1><<<GG, GB>>>(fb, Wf, rv, as3, ad3, hh, es, ed);
    gat_gather_k<32, 1><<<GBLK, 256>>>(rowptr, adj, hh, es, ed, b3, fa, 1);

    // ---- L4: GAT(32 -> 32, H=1) ----
    gemm2_k<32, 32, 1><<<GG, GB>>>(fa, W4, nullptr, as4, ad4, hh, es, ed);
    gat_gather_k<32, 1><<<GBLK, 256>>>(rowptr, adj, hh, es, ed, b4, fb, 1);

    // ---- BN4 + relu ----
    zero_k<<<1, 256>>>(bns, 2 * FMAX);
    bn_part<<<(NN + 127) / 128, 128>>>(fb, 32);
    bn_apply2<<<256, 256>>>(fb, g4, be4, 32, 1);

    // ---- L5: GAT(32 -> 128, H=1) ----
    gemm2_k<32, 128, 1><<<GG, GB>>>(fb, W5, nullptr, as5, ad5, hh, es, ed);
    gat_gather_k<128, 1><<<GBLK, 256>>>(rowptr, adj, hh, es, ed, b5, (float*)d_out, 0);
}